// round 8
// baseline (speedup 1.0000x reference)
#include <cuda_runtime.h>
#include <cuda_bf16.h>
#include <math.h>
#include <stdint.h>

// ---------------- problem constants ----------------
constexpr int B_  = 512;
constexpr int T_  = 200;
constexpr int D_  = 64;
constexpr int H_  = 256;
constexpr int BT  = B_ * T_;        // 102400 rows
constexpr int HT  = H_ * T_;        // 51200 flat dim
constexpr int C1_ = 1024;
constexpr int C2_ = 256;
constexpr int C3_ = 10;
constexpr int R1_ = 1024;
constexpr int G3  = 768;            // packed gates i,g,o (forget gate dead, c0=0)

constexpr size_t OUT_TOTAL_OFF = 0;
constexpr size_t OUT_CLASS_OFF = (size_t)BT * H_;
constexpr size_t OUT_REG_OFF   = OUT_CLASS_OFF + (size_t)B_ * C3_;

// ---------------- device scratch ----------------
__device__ float g_wsel0[G3 * D_];          // packed i,g,o rows fp32
__device__ float g_wsel1[G3 * H_];
__device__ float g_bsel0[G3], g_bsel1[G3];
__device__ float g_h0[(size_t)BT * H_];     // 105 MB fp32
__device__ float g_part[16 * 512 * 1024];   // split-K partials
__device__ float g_c1[B_ * C1_];
__device__ float g_c2[B_ * C2_];
__device__ float g_r [B_ * R1_];

// ---------------- PTX helpers (sm_80-compatible only) ----------------
__device__ __forceinline__ uint32_t smem_u32(const void* p) {
    uint32_t a;
    asm("{ .reg .u64 t; cvta.to.shared.u64 t, %1; cvt.u32.u64 %0, t; }" : "=r"(a) : "l"(p));
    return a;
}
__device__ __forceinline__ void ldsm_x4(uint32_t* r, uint32_t addr) {
    asm volatile("ldmatrix.sync.aligned.m8n8.x4.shared.b16 {%0,%1,%2,%3}, [%4];"
                 : "=r"(r[0]), "=r"(r[1]), "=r"(r[2]), "=r"(r[3]) : "r"(addr));
}
__device__ __forceinline__ void ldsm_x2(uint32_t* r, uint32_t addr) {
    asm volatile("ldmatrix.sync.aligned.m8n8.x2.shared.b16 {%0,%1}, [%2];"
                 : "=r"(r[0]), "=r"(r[1]) : "r"(addr));
}
__device__ __forceinline__ void mma_bf16(float* c, const uint32_t* a, const uint32_t* b) {
    asm volatile("mma.sync.aligned.m16n8k16.row.col.f32.bf16.bf16.f32 "
                 "{%0,%1,%2,%3}, {%4,%5,%6,%7}, {%8,%9}, {%0,%1,%2,%3};"
                 : "+f"(c[0]), "+f"(c[1]), "+f"(c[2]), "+f"(c[3])
                 : "r"(a[0]), "r"(a[1]), "r"(a[2]), "r"(a[3]), "r"(b[0]), "r"(b[1]));
}
__device__ __forceinline__ uint32_t pack_bf2(float a, float b) {
    __nv_bfloat162 t = __floats2bfloat162_rn(a, b);
    return *reinterpret_cast<uint32_t*>(&t);
}
__device__ __forceinline__ float bf_hi(float v) {
    __nv_bfloat16 h = __float2bfloat16(v);
    return __bfloat162float(h);
}
__device__ __forceinline__ float sigm(float x) { return 1.f / (1.f + expf(-x)); }

// ---------------- hi/lo-split HMMA GEMM (fp32 in, fp32 out) ----------------
// Standard mode: C[z][M,N] partial = A[M,K] * B[N,K]^T over k-slice z.
// Gate mode: for gate g in {i,g,o}: acc_g = A * Wsel[g*256+n, :]^T + bias,
//            h composed via smem stash; writes h[M,256] fp32.
// Tile 128x128x64, 512 threads, warp grid 4x4, warp tile 32x32.
// Two-stage SMEM, ONE __syncthreads per chunk (STS/LDG overlap MMA).
constexpr int HS_ROWB  = 144;               // 64 bf16 + 8 pad, bytes
constexpr int HS_TILE  = 128 * HS_ROWB;     // 18432
constexpr int HS_OPER  = 4 * HS_TILE;       // 73728 per stage
constexpr int HS_OPER2 = 2 * HS_OPER;       // 147456 two stages
constexpr int HS_STASH = 128 * 132 * 4;     // 67584 (128x128 fp32, pad)
constexpr int HS_SMEM_GATE = HS_OPER2 + HS_STASH;   // 215040

__global__ void __launch_bounds__(512, 1)
hs_gemm(const float* __restrict__ A, const float* __restrict__ Bw,
        float* __restrict__ C, const float* __restrict__ bias,
        int M, int N, int K, int kSlice, int gateMode)
{
    extern __shared__ __align__(128) char smem[];
    float* stash = reinterpret_cast<float*>(smem + HS_OPER2);
    const uint32_t sBase = smem_u32(smem);

    const int tid  = threadIdx.x;
    const int lane = tid & 31;
    const int warp = tid >> 5;
    const int wm   = warp >> 2;              // 0..3
    const int wn   = warp & 3;               // 0..3
    const int mBase = blockIdx.y * 128;
    const int nBase = blockIdx.x * 128;
    const int z     = gateMode ? 0 : blockIdx.z;
    const int kBeg  = z * kSlice;
    const int NC    = kSlice >> 6;

    const int aRow = (lane & 7) + ((lane >> 3) & 1) * 8;
    const int aCol = (lane >> 4) * 8;
    const int bRow = lane & 7;
    const int bCol = ((lane >> 3) & 1) * 8;

    // loader: 2048 float4 per operand tile, 4 per thread
    int lr[4], lc4[4];
#pragma unroll
    for (int t = 0; t < 4; t++) {
        int idx = tid + t * 512;
        lr[t]  = idx >> 4;        // 0..127
        lc4[t] = idx & 15;        // float4 unit within 64-col row
    }

    const int nGates = gateMode ? 3 : 1;

    for (int g = 0; g < nGates; g++) {
        const int rowOff = gateMode ? (g * 256 + nBase) : nBase;

        float acc[2][4][4];
#pragma unroll
        for (int mi = 0; mi < 2; mi++)
#pragma unroll
            for (int ni = 0; ni < 4; ni++)
#pragma unroll
                for (int q = 0; q < 4; q++) acc[mi][ni][q] = 0.f;

        float4 aR[4], bR[4];

        auto ldg_chunk = [&](int c) {
            int kk = kBeg + c * 64;
#pragma unroll
            for (int t = 0; t < 4; t++) {
                aR[t] = *reinterpret_cast<const float4*>(A  + (size_t)(mBase + lr[t]) * K + kk + lc4[t] * 4);
                bR[t] = *reinterpret_cast<const float4*>(Bw + (size_t)(rowOff + lr[t]) * K + kk + lc4[t] * 4);
            }
        };
        auto sts_split = [&](int stage) {
            char* pAhi = smem + stage * HS_OPER;
            char* pAlo = pAhi + HS_TILE;
            char* pBhi = pAhi + 2 * HS_TILE;
            char* pBlo = pAhi + 3 * HS_TILE;
#pragma unroll
            for (int t = 0; t < 4; t++) {
                int off = lr[t] * HS_ROWB + lc4[t] * 8;
                float4 v = aR[t];
                float hx = bf_hi(v.x), hy = bf_hi(v.y), hz = bf_hi(v.z), hw = bf_hi(v.w);
                *reinterpret_cast<uint2*>(pAhi + off) =
                    make_uint2(pack_bf2(hx, hy), pack_bf2(hz, hw));
                *reinterpret_cast<uint2*>(pAlo + off) =
                    make_uint2(pack_bf2(v.x - hx, v.y - hy), pack_bf2(v.z - hz, v.w - hw));
                v = bR[t];
                hx = bf_hi(v.x); hy = bf_hi(v.y); hz = bf_hi(v.z); hw = bf_hi(v.w);
                *reinterpret_cast<uint2*>(pBhi + off) =
                    make_uint2(pack_bf2(hx, hy), pack_bf2(hz, hw));
                *reinterpret_cast<uint2*>(pBlo + off) =
                    make_uint2(pack_bf2(v.x - hx, v.y - hy), pack_bf2(v.z - hz, v.w - hw));
            }
        };

        // prologue: stage 0 ready, chunk 1 in regs
        ldg_chunk(0);
        sts_split(0);
        if (NC > 1) ldg_chunk(1);
        __syncthreads();

        for (int c = 0; c < NC; c++) {
            // overlap: fill the other stage + fetch chunk c+2 while MMA(c) runs
            if (c + 1 < NC) sts_split((c + 1) & 1);
            if (c + 2 < NC) ldg_chunk(c + 2);

            uint32_t sAhi = sBase + (c & 1) * HS_OPER;
            uint32_t sAlo = sAhi + HS_TILE;
            uint32_t sBhi = sAhi + 2 * HS_TILE;
            uint32_t sBlo = sAhi + 3 * HS_TILE;
#pragma unroll
            for (int ks = 0; ks < 4; ks++) {
                uint32_t ah[2][4], al[2][4], bh[4][2], bl[4][2];
#pragma unroll
                for (int mi = 0; mi < 2; mi++) {
                    uint32_t ro = (wm * 32 + mi * 16 + aRow) * HS_ROWB + (ks * 16 + aCol) * 2;
                    ldsm_x4(ah[mi], sAhi + ro);
                    ldsm_x4(al[mi], sAlo + ro);
                }
#pragma unroll
                for (int ni = 0; ni < 4; ni++) {
                    uint32_t ro = (wn * 32 + ni * 8 + bRow) * HS_ROWB + (ks * 16 + bCol) * 2;
                    ldsm_x2(bh[ni], sBhi + ro);
                    ldsm_x2(bl[ni], sBlo + ro);
                }
#pragma unroll
                for (int mi = 0; mi < 2; mi++)
#pragma unroll
                    for (int ni = 0; ni < 4; ni++) {
                        mma_bf16(acc[mi][ni], ah[mi], bh[ni]);
                        mma_bf16(acc[mi][ni], ah[mi], bl[ni]);
                        mma_bf16(acc[mi][ni], al[mi], bh[ni]);
                    }
            }
            __syncthreads();
        }

        // ---- epilogue ----
        if (!gateMode) {
            float* Cp = C + (size_t)z * M * N;
#pragma unroll
            for (int mi = 0; mi < 2; mi++) {
                int r0 = mBase + wm * 32 + mi * 16 + (lane >> 2);
#pragma unroll
                for (int ni = 0; ni < 4; ni++) {
                    int col = nBase + wn * 32 + ni * 8 + (lane & 3) * 2;
                    *reinterpret_cast<float2*>(&Cp[(size_t)r0 * N + col]) =
                        make_float2(acc[mi][ni][0], acc[mi][ni][1]);
                    *reinterpret_cast<float2*>(&Cp[(size_t)(r0 + 8) * N + col]) =
                        make_float2(acc[mi][ni][2], acc[mi][ni][3]);
                }
            }
        } else {
#pragma unroll
            for (int mi = 0; mi < 2; mi++)
#pragma unroll
                for (int ni = 0; ni < 4; ni++)
#pragma unroll
                    for (int q = 0; q < 4; q++) {
                        int rl = wm * 32 + mi * 16 + (lane >> 2) + ((q >= 2) ? 8 : 0);
                        int cl = wn * 32 + ni * 8 + (lane & 3) * 2 + (q & 1);
                        float v = acc[mi][ni][q] + bias[rowOff + cl];
                        int si = rl * 132 + cl;
                        if (g == 0)      stash[si] = sigm(v);
                        else if (g == 1) stash[si] *= tanhf(v);
                        else {
                            float h = sigm(v) * tanhf(stash[si]);
                            C[(size_t)(mBase + rl) * H_ + nBase + cl] = h;
                        }
                    }
        }
    }
}

// ---------------- small kernels ----------------
__global__ void make_wsel(const float* __restrict__ W, const float* __restrict__ bih,
                          const float* __restrict__ bhh, float* __restrict__ Wsel,
                          float* __restrict__ bsel, int Kd)
{
    int idx = blockIdx.x * blockDim.x + threadIdx.x;
    int total = G3 * Kd;
    if (idx < total) {
        int j = idx / Kd;
        int c = idx - j * Kd;
        int src = j + ((j >= 256) ? 256 : 0);
        Wsel[idx] = W[src * Kd + c];
    }
    if (idx < G3) {
        int src = idx + ((idx >= 256) ? 256 : 0);
        bsel[idx] = bih[src] + bhh[src];
    }
}

__global__ void reduce_bias_act(const float* __restrict__ part, int S, int MN, int N,
                                const float* __restrict__ bias, float* __restrict__ out, int relu)
{
    int idx = blockIdx.x * blockDim.x + threadIdx.x;
    if (idx >= MN) return;
    float s = 0.f;
    for (int i = 0; i < S; i++) s += part[(size_t)i * MN + idx];
    s += bias[idx % N];
    if (relu) s = fmaxf(s, 0.f);
    out[idx] = s;
}

// ---------------- fp32 SGEMM (small fc layers) ----------------
__global__ void __launch_bounds__(256, 2)
sgemm_nt(const float* __restrict__ A, const float* __restrict__ B,
         float* __restrict__ C, int M, int N, int K, int kSlice)
{
    constexpr int BM = 128, BN = 128, BK = 8;
    __shared__ float As[BK][BM];
    __shared__ float Bs[BK][BN];
    const int tid = threadIdx.x;
    const int mBase = blockIdx.y * BM;
    const int nBase = blockIdx.x * BN;
    const int z = blockIdx.z;
    const int kBeg = z * kSlice;
    const int kEnd = kBeg + kSlice;
    const int lr = tid >> 1;
    const int lc = (tid & 1) * 4;
    const int tr = (tid >> 4) * 8;
    const int tc = (tid & 15) * 8;
    float acc[8][8];
#pragma unroll
    for (int i = 0; i < 8; i++)
#pragma unroll
        for (int j = 0; j < 8; j++) acc[i][j] = 0.f;
    const float* Aptr = A + (size_t)(mBase + lr) * K;
    const bool bvalid = (nBase + lr) < N;
    const float* Bptr = B + (bvalid ? (size_t)(nBase + lr) * K : 0);
    for (int k0 = kBeg; k0 < kEnd; k0 += BK) {
        float4 a4 = *reinterpret_cast<const float4*>(Aptr + k0 + lc);
        float4 b4 = make_float4(0.f, 0.f, 0.f, 0.f);
        if (bvalid) b4 = *reinterpret_cast<const float4*>(Bptr + k0 + lc);
        As[lc + 0][lr] = a4.x; As[lc + 1][lr] = a4.y;
        As[lc + 2][lr] = a4.z; As[lc + 3][lr] = a4.w;
        Bs[lc + 0][lr] = b4.x; Bs[lc + 1][lr] = b4.y;
        Bs[lc + 2][lr] = b4.z; Bs[lc + 3][lr] = b4.w;
        __syncthreads();
#pragma unroll
        for (int kk = 0; kk < BK; kk++) {
            float rm[8], rn[8];
#pragma unroll
            for (int i = 0; i < 8; i++) rm[i] = As[kk][tr + i];
#pragma unroll
            for (int j = 0; j < 8; j++) rn[j] = Bs[kk][tc + j];
#pragma unroll
            for (int i = 0; i < 8; i++)
#pragma unroll
                for (int j = 0; j < 8; j++) acc[i][j] = fmaf(rm[i], rn[j], acc[i][j]);
        }
        __syncthreads();
    }
    float* Cp = C + (size_t)z * M * N;
#pragma unroll
    for (int i = 0; i < 8; i++) {
        const size_t rowOff = (size_t)(mBase + tr + i) * N;
#pragma unroll
        for (int j = 0; j < 8; j++) {
            int col = nBase + tc + j;
            if (col < N) Cp[rowOff + col] = acc[i][j];
        }
    }
}

__global__ void fc3_kernel(const float* __restrict__ x, const float* __restrict__ W,
                           const float* __restrict__ b, float* __restrict__ out)
{
    int idx = blockIdx.x * blockDim.x + threadIdx.x;
    if (idx >= B_ * C3_) return;
    int m = idx / C3_;
    int n = idx - m * C3_;
    const float* xr = x + m * C2_;
    const float* wr = W + n * C2_;
    float s = 0.f;
#pragma unroll 4
    for (int k = 0; k < C2_; k++) s = fmaf(xr[k], wr[k], s);
    out[idx] = s + b[n];
}

// ---------------- launch ----------------
extern "C" void kernel_launch(void* const* d_in, const int* in_sizes, int n_in,
                              void* d_out_v, int out_size)
{
    const float* x     = (const float*)d_in[0];
    const float* W_ih0 = (const float*)d_in[1];
    const float* b_ih0 = (const float*)d_in[2];
    const float* b_hh0 = (const float*)d_in[3];
    const float* W_ih1 = (const float*)d_in[4];
    const float* b_ih1 = (const float*)d_in[5];
    const float* b_hh1 = (const float*)d_in[6];
    const float* fc1_w = (const float*)d_in[7];
    const float* fc1_b = (const float*)d_in[8];
    const float* fc2_w = (const float*)d_in[9];
    const float* fc2_b = (const float*)d_in[10];
    const float* fc3_w = (const float*)d_in[11];
    const float* fc3_b = (const float*)d_in[12];
    const float* fc4_w = (const float*)d_in[13];
    const float* fc4_b = (const float*)d_in[14];
    const float* fc5_w = (const float*)d_in[15];
    const float* fc5_b = (const float*)d_in[16];
    float* d_out = (float*)d_out_v;

    cudaFuncSetAttribute(hs_gemm, cudaFuncAttributeMaxDynamicSharedMemorySize, HS_SMEM_GATE);

    float *wsel0, *wsel1, *bsel0, *bsel1, *h0, *part, *c1, *c2, *r;
    cudaGetSymbolAddress((void**)&wsel0, g_wsel0);
    cudaGetSymbolAddress((void**)&wsel1, g_wsel1);
    cudaGetSymbolAddress((void**)&bsel0, g_bsel0);
    cudaGetSymbolAddress((void**)&bsel1, g_bsel1);
    cudaGetSymbolAddress((void**)&h0,    g_h0);
    cudaGetSymbolAddress((void**)&part,  g_part);
    cudaGetSymbolAddress((void**)&c1,    g_c1);
    cudaGetSymbolAddress((void**)&c2,    g_c2);
    cudaGetSymbolAddress((void**)&r,     g_r);

    // pack gate weights (fp32, skip forget gate)
    make_wsel<<<(G3 * D_ + 255) / 256, 256>>>(W_ih0, b_ih0, b_hh0, wsel0, bsel0, D_);
    make_wsel<<<(G3 * H_ + 255) / 256, 256>>>(W_ih1, b_ih1, b_hh1, wsel1, bsel1, H_);

    // LSTM layer 0 (gate mode): h0 = lstm(x @ Wsel0^T + bsel0)
    hs_gemm<<<dim3(2, BT / 128, 1), 512, HS_SMEM_GATE>>>(
        x, wsel0, h0, bsel0, BT, H_, D_, D_, 1);

    // LSTM layer 1 (gate mode): out_total = lstm(h0 @ Wsel1^T + bsel1) -> d_out fp32
    hs_gemm<<<dim3(2, BT / 128, 1), 512, HS_SMEM_GATE>>>(
        h0, wsel1, d_out + OUT_TOTAL_OFF, bsel1, BT, H_, H_, H_, 1);

    const float* flat = d_out + OUT_TOTAL_OFF;  // [512, 51200] fp32

    // fc1 (split-K=16) + relu
    hs_gemm<<<dim3(C1_ / 128, B_ / 128, 16), 512, HS_OPER2>>>(
        flat, fc1_w, part, nullptr, B_, C1_, HT, HT / 16, 0);
    reduce_bias_act<<<(B_ * C1_ + 255) / 256, 256>>>(part, 16, B_ * C1_, C1_, fc1_b, c1, 1);

    // fc2 (fp32 path) + relu
    sgemm_nt<<<dim3(C2_ / 128, B_ / 128, 4), 256>>>(c1, fc2_w, part, B_, C2_, C1_, C1_ / 4);
    reduce_bias_act<<<(B_ * C2_ + 255) / 256, 256>>>(part, 4, B_ * C2_, C2_, fc2_b, c2, 1);

    // fc3 -> class output
    fc3_kernel<<<(B_ * C3_ + 255) / 256, 256>>>(c2, fc3_w, fc3_b, d_out + OUT_CLASS_OFF);

    // fc4 (split-K=16) + relu
    hs_gemm<<<dim3(R1_ / 128, B_ / 128, 16), 512, HS_OPER2>>>(
        flat, fc4_w, part, nullptr, B_, R1_, HT, HT / 16, 0);
    reduce_bias_act<<<(B_ * R1_ + 255) / 256, 256>>>(part, 16, B_ * R1_, R1_, fc4_b, r, 1);

    // fc5 (fp32 path, N=200 ragged) -> regression output
    sgemm_nt<<<dim3((T_ + 127) / 128, B_ / 128, 4), 256>>>(r, fc5_w, part, B_, T_, R1_, R1_ / 4);
    reduce_bias_act<<<(B_ * T_ + 255) / 256, 256>>>(part, 4, B_ * T_, T_, fc5_b,
                                                    d_out + OUT_REG_OFF, 0);
}